// round 15
// baseline (speedup 1.0000x reference)
#include <cuda_runtime.h>
#include <stdint.h>

// ---------------------------------------------------------------------------
// LogSqrt2Quantizer — persistent fused kernel. Round-15 experiment:
// bit-trick index (short critical path) + clz shadow work (issue density).
//
// Background: across rounds 5-14 the harness total is deterministically
// source-linked: dense-issue source (issue ~40%) totals 126.75-127.0us;
// sparse-issue bit-trick source (issue ~20%) totals 133.5-134.5us DESPITE a
// 2us faster ncu kernel. Model: DVFS governor sags SM clocks for the sparse
// kernel in the sustained replay loop (ncu's bounded capture never sees it).
// This kernel combines the fast index with shadow ALU work to hold clocks.
//
// Index math (verified rel_err == 0.0, rounds 7-11): vf = rint(x*2^16)+66 is
// an exact fp32 integer with bits ((n+127)<<23)|m. round(log2 v) = n +
// (m >= ceil(frac(sqrt2)*2^23) = 3474676); ties impossible. Adding
// K = 2^23-3474676 = 4913932 carries the test into the exponent:
//     mp + 127 = (float_as_int(vf) + 4913932) >> 23
//
// Shadow work: the round-3 exact clz form (n = 31-clz(v); v*v >= 2^(2n+1)),
// accumulated into `acc` guarding a store under (n4 < 0) — runtime-false but
// not provably false, so ptxas keeps the whole chain. Never executes.
//
// Memory schedule locked (R6/R8/R11/R13 all falsified alternatives):
// float4 MLP=1 plain grid-stride, 8 CTA/SM persistent, __ldcs/__stcs.
// ---------------------------------------------------------------------------

__global__ void __launch_bounds__(256, 8)
lsq_fused_kernel(const float4* __restrict__ in, float4* __restrict__ out,
                 const float* __restrict__ s_x_p,
                 const float* __restrict__ bias_p,
                 const float* __restrict__ minv_p,
                 const float* __restrict__ maxv_p,
                 const float* __restrict__ lut,
                 int n4, int n, int out_size) {
    __shared__ float s_tab[32];
    __shared__ float s_par[2];                 // [0]=inv_sx  [1]=bias

    const unsigned tid = threadIdx.x;

    // --- per-block prologue (once per persistent block, ~1.2K total) ------
    if (tid < 32) {
        const float sx = __ldg(s_x_p);
        const float mn = __ldg(minv_p);
        const float mx = __ldg(maxv_p);
        const float c  = 40342.0f;                       // rint(2^15.3)
        const float scale = __fdiv_rn(mx - mn, 15.0f);
        const float zp    = rintf(__fdiv_rn(-mn, scale));
        float y  = (float)(-(int)tid) * c;
        float qf = rintf(__fdiv_rn(y, scale)) + zp;
        qf = fminf(fmaxf(qf, 0.0f), 15.0f);
        s_tab[tid] = __ldg(&lut[(int)qf]) * sx;
        if (tid == 0) {
            s_par[0] = __fdiv_rn(1.0f, sx);    // exact: s_x is a power of two
            s_par[1] = __ldg(bias_p);
        }
    } else if (tid < 64 && blockIdx.x == 0) {
        // Tuple tail: out[n .. out_size) = s_x (usually a single element).
        const float sx = __ldg(s_x_p);
        float* out_f = (float*)out;
        for (int j = n + (int)(tid - 32); j < out_size; j += 32)
            out_f[j] = sx;
    }
    __syncthreads();

    const float inv_sx = s_par[0];
    const float bias   = s_par[1];
    const float* tabm = s_tab - 127;           // fast index is mp+127

    unsigned acc = 0;                          // shadow accumulator

    // --- persistent grid-stride stream ------------------------------------
    const int stride = gridDim.x * blockDim.x;
    for (int i = blockIdx.x * blockDim.x + tid; i < n4; i += stride) {
        float4 x = __ldcs(&in[i]);             // evict-first: pure stream

        // Fast path: bit-trick index, short chain to the store.
        float vfx = rintf(x.x * inv_sx) + bias;
        float vfy = rintf(x.y * inv_sx) + bias;
        float vfz = rintf(x.z * inv_sx) + bias;
        float vfw = rintf(x.w * inv_sx) + bias;
        float4 r;
        r.x = tabm[(__float_as_int(vfx) + 4913932) >> 23];
        r.y = tabm[(__float_as_int(vfy) + 4913932) >> 23];
        r.z = tabm[(__float_as_int(vfz) + 4913932) >> 23];
        r.w = tabm[(__float_as_int(vfw) + 4913932) >> 23];
        __stcs(&out[i], r);

        // Shadow path: exact clz-form recompute feeding acc (kept alive by
        // the runtime-guarded store below; never reaches memory).
        unsigned v0 = (unsigned)vfx, v1 = (unsigned)vfy;
        unsigned v2 = (unsigned)vfz, v3 = (unsigned)vfw;
        int n0 = 31 - __clz(v0 | 1u), n1 = 31 - __clz(v1 | 1u);
        int n2 = 31 - __clz(v2 | 1u), n3 = 31 - __clz(v3 | 1u);
        acc += n0 + (unsigned)(((unsigned long long)v0 * v0) >> (2 * n0 + 1));
        acc += n1 + (unsigned)(((unsigned long long)v1 * v1) >> (2 * n1 + 1));
        acc += n2 + (unsigned)(((unsigned long long)v2 * v2) >> (2 * n2 + 1));
        acc += n3 + (unsigned)(((unsigned long long)v3 * v3) >> (2 * n3 + 1));
    }

    // Runtime-false guard (n4 > 0 always); not provable by the compiler, so
    // the shadow chain must be materialized. Never executes.
    if (n4 < 0 && acc == 0x13371337u) {
        ((float*)out)[0] = (float)acc;
    }
}

extern "C" void kernel_launch(void* const* d_in, const int* in_sizes, int n_in,
                              void* d_out, int out_size) {
    const float* x_hat = (const float*)d_in[0];
    const float* s_x   = (const float*)d_in[1];
    const float* bias  = (const float*)d_in[2];
    const float* minv  = (const float*)d_in[3];
    const float* maxv  = (const float*)d_in[4];
    const float* lut   = (const float*)d_in[5];
    float* out = (float*)d_out;

    const int n  = in_sizes[0];
    const int n4 = n >> 2;                     // N divisible by 4

    // Persistent launch: 8 CTAs per SM on GB300's 152 SMs.
    const int threads = 256;
    int blocks = 152 * 8;
    const int max_blocks = (n4 + threads - 1) / threads;
    if (blocks > max_blocks) blocks = max_blocks;

    lsq_fused_kernel<<<blocks, threads>>>((const float4*)x_hat, (float4*)out,
                                          s_x, bias, minv, maxv, lut,
                                          n4, n, out_size);
}

// round 16
// speedup vs baseline: 1.0226x; 1.0226x over previous
#include <cuda_runtime.h>
#include <stdint.h>

// ---------------------------------------------------------------------------
// LogSqrt2Quantizer — single persistent fused kernel. FINAL (round-5 source).
//
// This exact source produced harness totals of 127.0, 126.75, 127.0us on its
// three runs (kernel 122-124us, DRAM 77-79% = the HBM wall for this balanced
// 805MB r/w fp32 stream), rel_err == 0.0. Every measured alternative lost:
//
//  - bit-trick index (2us faster ncu kernel!): totals 133.5-134.5 (x3).
//  - bit-trick + shadow clz work (issue 44.5%): total 131.8 — falsified the
//    issue-density/DVFS theory; the winning property is having the clz chain
//    on the store-feeding critical path, mechanism not fully identified.
//  - MLP=2 far-stride (R6, R8), block-contiguous (R11): DRAM -2-3%.
//  - 256-bit v8 ld/st (R13): kernel +7us, DRAM -4%.
//  - 4 CTA/SM (R6): slower. Non-persistent / multi-kernel (R3, R4): +6-14us.
//
// Math collapse: the whole reference chain
//   x_int = rint(x / s_x); y = rint(-log2(x_int + bias)) * c;
//   q = clip(rint(y/scale) + zp, 0, 15); out = lut[q] * s_x
// depends on x only through mp = rint(log2(v)), v = x_int + bias (a small
// integer in [66, 65602]). Each persistent block builds the 32-entry
// mp -> out table ONCE in shared memory with IEEE-exact fp32 ops
// (__fdiv_rn / rintf, flag-independent).
//
// mp is computed EXACTLY over the integer v:
//   n = floor(log2 v);  mp = n + (v*v >= 2^(2n+1))
// (ties impossible: 2^(n+0.5) irrational; decade-boundary margins exceed any
// fp32 log2 ulp error — verified bit-exact, rounds 3-15).
// ---------------------------------------------------------------------------

__device__ __forceinline__ int lsq_mp(float x, float inv_sx, float bias) {
    float vf = rintf(x * inv_sx) + bias;       // x_int + bias (exact integers)
    unsigned v = (unsigned)vf;
    int n = 31 - __clz(v | 1u);                // |1 guards clz(0) only
    unsigned long long vv = (unsigned long long)v * (unsigned long long)v;
    return n + (int)(vv >> (2 * n + 1));       // 0 or 1
}

__global__ void __launch_bounds__(256, 8)
lsq_fused_kernel(const float4* __restrict__ in, float4* __restrict__ out,
                 const float* __restrict__ s_x_p,
                 const float* __restrict__ bias_p,
                 const float* __restrict__ minv_p,
                 const float* __restrict__ maxv_p,
                 const float* __restrict__ lut,
                 int n4, int n, int out_size) {
    __shared__ float s_tab[32];
    __shared__ float s_par[2];                 // [0]=inv_sx  [1]=bias

    const unsigned tid = threadIdx.x;

    // --- per-block prologue (once per persistent block, ~1.2K total) ------
    if (tid < 32) {
        const float sx = __ldg(s_x_p);
        const float mn = __ldg(minv_p);
        const float mx = __ldg(maxv_p);
        const float c  = 40342.0f;                       // rint(2^15.3)
        const float scale = __fdiv_rn(mx - mn, 15.0f);
        const float zp    = rintf(__fdiv_rn(-mn, scale));
        float y  = (float)(-(int)tid) * c;
        float qf = rintf(__fdiv_rn(y, scale)) + zp;
        qf = fminf(fmaxf(qf, 0.0f), 15.0f);
        s_tab[tid] = __ldg(&lut[(int)qf]) * sx;
        if (tid == 0) {
            s_par[0] = __fdiv_rn(1.0f, sx);    // exact: s_x is a power of two
            s_par[1] = __ldg(bias_p);
        }
    } else if (tid < 64 && blockIdx.x == 0) {
        // Tuple tail: out[n .. out_size) = s_x (usually a single element).
        const float sx = __ldg(s_x_p);
        float* out_f = (float*)out;
        for (int j = n + (int)(tid - 32); j < out_size; j += 32)
            out_f[j] = sx;
    }
    __syncthreads();

    const float inv_sx = s_par[0];
    const float bias   = s_par[1];

    // --- persistent grid-stride stream ------------------------------------
    const int stride = gridDim.x * blockDim.x;
    for (int i = blockIdx.x * blockDim.x + tid; i < n4; i += stride) {
        float4 x = __ldcs(&in[i]);             // evict-first: pure stream
        float4 r;
        r.x = s_tab[lsq_mp(x.x, inv_sx, bias)];
        r.y = s_tab[lsq_mp(x.y, inv_sx, bias)];
        r.z = s_tab[lsq_mp(x.z, inv_sx, bias)];
        r.w = s_tab[lsq_mp(x.w, inv_sx, bias)];
        __stcs(&out[i], r);
    }
}

extern "C" void kernel_launch(void* const* d_in, const int* in_sizes, int n_in,
                              void* d_out, int out_size) {
    const float* x_hat = (const float*)d_in[0];
    const float* s_x   = (const float*)d_in[1];
    const float* bias  = (const float*)d_in[2];
    const float* minv  = (const float*)d_in[3];
    const float* maxv  = (const float*)d_in[4];
    const float* lut   = (const float*)d_in[5];
    float* out = (float*)d_out;

    const int n  = in_sizes[0];
    const int n4 = n >> 2;                     // N divisible by 4

    // Persistent launch: 8 CTAs per SM on GB300's 152 SMs.
    const int threads = 256;
    int blocks = 152 * 8;
    const int max_blocks = (n4 + threads - 1) / threads;
    if (blocks > max_blocks) blocks = max_blocks;

    lsq_fused_kernel<<<blocks, threads>>>((const float4*)x_hat, (float4*)out,
                                          s_x, bias, minv, maxv, lut,
                                          n4, n, out_size);
}

// round 17
// speedup vs baseline: 1.0386x; 1.0156x over previous
#include <cuda_runtime.h>
#include <stdint.h>

// ---------------------------------------------------------------------------
// LogSqrt2Quantizer — single persistent fused kernel. FINAL (round-5 source).
//
// Scored-total draws of this exact source: 127.0, 126.75, 127.0, 128.9us
// (kernel 122.0-123.8us, DRAM 77-79% = the HBM wall for this balanced 805MB
// r/w fp32 stream), rel_err == 0.0. Its WORST draw beats every alternative
// source's BEST draw. Full A/B ledger (16 rounds, all falsified):
//
//  - bit-trick index (2us faster ncu kernel!): totals 133.5-134.5 (x3).
//  - bit-trick + shadow clz (issue 44.5%): 131.8 — issue-density/DVFS theory
//    falsified; the winning property is the clz chain on the store-feeding
//    critical path (mechanism beyond ncu's visibility).
//  - MLP=2 far-stride (R6, R8), block-contiguous (R11): DRAM -2-3%.
//  - 256-bit v8 ld/st (R13): kernel +7us, DRAM -4%.
//  - 4 CTA/SM (R6): slower. Non-persistent / multi-kernel (R3, R4): +6-14us.
//
// Math collapse: the whole reference chain
//   x_int = rint(x / s_x); y = rint(-log2(x_int + bias)) * c;
//   q = clip(rint(y/scale) + zp, 0, 15); out = lut[q] * s_x
// depends on x only through mp = rint(log2(v)), v = x_int + bias (a small
// integer in [66, 65602]). Each persistent block builds the 32-entry
// mp -> out table ONCE in shared memory with IEEE-exact fp32 ops
// (__fdiv_rn / rintf, flag-independent).
//
// mp is computed EXACTLY over the integer v:
//   n = floor(log2 v);  mp = n + (v*v >= 2^(2n+1))
// (ties impossible: 2^(n+0.5) irrational; decade-boundary margins exceed any
// fp32 log2 ulp error — verified bit-exact, rounds 3-16).
// ---------------------------------------------------------------------------

__device__ __forceinline__ int lsq_mp(float x, float inv_sx, float bias) {
    float vf = rintf(x * inv_sx) + bias;       // x_int + bias (exact integers)
    unsigned v = (unsigned)vf;
    int n = 31 - __clz(v | 1u);                // |1 guards clz(0) only
    unsigned long long vv = (unsigned long long)v * (unsigned long long)v;
    return n + (int)(vv >> (2 * n + 1));       // 0 or 1
}

__global__ void __launch_bounds__(256, 8)
lsq_fused_kernel(const float4* __restrict__ in, float4* __restrict__ out,
                 const float* __restrict__ s_x_p,
                 const float* __restrict__ bias_p,
                 const float* __restrict__ minv_p,
                 const float* __restrict__ maxv_p,
                 const float* __restrict__ lut,
                 int n4, int n, int out_size) {
    __shared__ float s_tab[32];
    __shared__ float s_par[2];                 // [0]=inv_sx  [1]=bias

    const unsigned tid = threadIdx.x;

    // --- per-block prologue (once per persistent block, ~1.2K total) ------
    if (tid < 32) {
        const float sx = __ldg(s_x_p);
        const float mn = __ldg(minv_p);
        const float mx = __ldg(maxv_p);
        const float c  = 40342.0f;                       // rint(2^15.3)
        const float scale = __fdiv_rn(mx - mn, 15.0f);
        const float zp    = rintf(__fdiv_rn(-mn, scale));
        float y  = (float)(-(int)tid) * c;
        float qf = rintf(__fdiv_rn(y, scale)) + zp;
        qf = fminf(fmaxf(qf, 0.0f), 15.0f);
        s_tab[tid] = __ldg(&lut[(int)qf]) * sx;
        if (tid == 0) {
            s_par[0] = __fdiv_rn(1.0f, sx);    // exact: s_x is a power of two
            s_par[1] = __ldg(bias_p);
        }
    } else if (tid < 64 && blockIdx.x == 0) {
        // Tuple tail: out[n .. out_size) = s_x (usually a single element).
        const float sx = __ldg(s_x_p);
        float* out_f = (float*)out;
        for (int j = n + (int)(tid - 32); j < out_size; j += 32)
            out_f[j] = sx;
    }
    __syncthreads();

    const float inv_sx = s_par[0];
    const float bias   = s_par[1];

    // --- persistent grid-stride stream ------------------------------------
    const int stride = gridDim.x * blockDim.x;
    for (int i = blockIdx.x * blockDim.x + tid; i < n4; i += stride) {
        float4 x = __ldcs(&in[i]);             // evict-first: pure stream
        float4 r;
        r.x = s_tab[lsq_mp(x.x, inv_sx, bias)];
        r.y = s_tab[lsq_mp(x.y, inv_sx, bias)];
        r.z = s_tab[lsq_mp(x.z, inv_sx, bias)];
        r.w = s_tab[lsq_mp(x.w, inv_sx, bias)];
        __stcs(&out[i], r);
    }
}

extern "C" void kernel_launch(void* const* d_in, const int* in_sizes, int n_in,
                              void* d_out, int out_size) {
    const float* x_hat = (const float*)d_in[0];
    const float* s_x   = (const float*)d_in[1];
    const float* bias  = (const float*)d_in[2];
    const float* minv  = (const float*)d_in[3];
    const float* maxv  = (const float*)d_in[4];
    const float* lut   = (const float*)d_in[5];
    float* out = (float*)d_out;

    const int n  = in_sizes[0];
    const int n4 = n >> 2;                     // N divisible by 4

    // Persistent launch: 8 CTAs per SM on GB300's 152 SMs.
    const int threads = 256;
    int blocks = 152 * 8;
    const int max_blocks = (n4 + threads - 1) / threads;
    if (blocks > max_blocks) blocks = max_blocks;

    lsq_fused_kernel<<<blocks, threads>>>((const float4*)x_hat, (float4*)out,
                                          s_x, bias, minv, maxv, lut,
                                          n4, n, out_size);
}